// round 17
// baseline (speedup 1.0000x reference)
#include <cuda_runtime.h>
#include <cuda_fp16.h>
#include <cstdint>

// Problem constants
#define BATCH 2
#define SEQ   2048
#define DMODEL 1024
#define NHEAD 16
#define HDIM  64
#define MROWS (BATCH*SEQ)          // 4096
#define NEG_INF_V (-1.0e9f)
#define QSCALE (0.125f * 1.4426950408889634f)   // 1/sqrt(64) * log2(e)

// ---------------- scratch (no allocation allowed) ----------------
__device__ __half g_Q[BATCH*NHEAD*SEQ*HDIM];   // [B,H,L,Hd] scaled by QSCALE
__device__ __half g_K[BATCH*NHEAD*SEQ*HDIM];   // [B,H,L,Hd]
__device__ __half g_V[BATCH*NHEAD*SEQ*HDIM];   // [B,H,L,Hd]
__device__ __half g_O[BATCH*SEQ*DMODEL];       // [B,L,D]

// ---------------- helpers ----------------
__device__ __forceinline__ uint32_t pack2(float a, float b) {
    __half2 h = __floats2half2_rn(a, b);
    return *(uint32_t*)&h;
}
__device__ __forceinline__ float ex2f(float x) {
    float r;
    asm("ex2.approx.ftz.f32 %0, %1;" : "=f"(r) : "f"(x));
    return r;
}
__device__ __forceinline__ void mma_f16(float c[4], uint32_t a0, uint32_t a1,
                                        uint32_t a2, uint32_t a3,
                                        uint32_t b0, uint32_t b1) {
    asm volatile(
        "mma.sync.aligned.m16n8k16.row.col.f32.f16.f16.f32 "
        "{%0,%1,%2,%3},{%4,%5,%6,%7},{%8,%9},{%0,%1,%2,%3};"
        : "+f"(c[0]), "+f"(c[1]), "+f"(c[2]), "+f"(c[3])
        : "r"(a0), "r"(a1), "r"(a2), "r"(a3), "r"(b0), "r"(b1));
}
__device__ __forceinline__ void ldsm_x4(uint32_t& r0, uint32_t& r1,
                                        uint32_t& r2, uint32_t& r3, uint32_t addr) {
    asm volatile("ldmatrix.sync.aligned.m8n8.x4.shared.b16 {%0,%1,%2,%3}, [%4];"
                 : "=r"(r0), "=r"(r1), "=r"(r2), "=r"(r3) : "r"(addr));
}
__device__ __forceinline__ void ldsm_x4_t(uint32_t& r0, uint32_t& r1,
                                          uint32_t& r2, uint32_t& r3, uint32_t addr) {
    asm volatile("ldmatrix.sync.aligned.m8n8.x4.trans.shared.b16 {%0,%1,%2,%3}, [%4];"
                 : "=r"(r0), "=r"(r1), "=r"(r2), "=r"(r3) : "r"(addr));
}
__device__ __forceinline__ uint32_t smem_u32(const void* p) {
    uint32_t a;
    asm("{ .reg .u64 t; cvta.to.shared.u64 t, %1; cvt.u32.u64 %0, t; }" : "=r"(a) : "l"(p));
    return a;
}
__device__ __forceinline__ void cp16(uint32_t dst, const void* src) {
    asm volatile("cp.async.cg.shared.global [%0], [%1], 16;" :: "r"(dst), "l"(src) : "memory");
}
__device__ __forceinline__ void cp_commit() {
    asm volatile("cp.async.commit_group;" ::: "memory");
}
__device__ __forceinline__ void cp_wait1() {
    asm volatile("cp.async.wait_group 1;" ::: "memory");
}
__device__ __forceinline__ void cp_wait2() {
    asm volatile("cp.async.wait_group 2;" ::: "memory");
}

// =================================================================
// fp16 tensor GEMM v4: inline fp32->fp16 conversion during staging
//   (prep kernel eliminated). 512 threads = 16 warps (4m x 4n) of
//   32x32, CTA tile 128x128, BK=64, 3 smem buffers, 1 barrier/chunk:
//     loop: [compute c from buf st][stage c+2 -> buf st+2][bar]
//   ldmatrix fragments, stride 72 halves (conflict-free).
// MODE 0: A,W fp32 (z selects q/k/v + Wq/Wk/Wv);
//         z0 -> g_Q (x QSCALE), z1 -> g_K, z2 -> g_V
// MODE 1: A fp16 (g_O), W fp32 (Wo); writes fp32 out.
// =================================================================
#define GSTR 72
#define GBUFH (128*GSTR)                // 9216 halves per operand buffer
#define GSTG  (2*GBUFH*2)               // buffer bytes (A+B) = 36864
#define GT_SMEM_BYTES (3*GSTG)          // 110592 B

template<int MODE>
__global__ __launch_bounds__(512, 2)
void gemm_mma(const float* __restrict__ Af0, const float* __restrict__ Af1,
              const float* __restrict__ Af2,
              const float* __restrict__ Wf0, const float* __restrict__ Wf1,
              const float* __restrict__ Wf2,
              const __half* __restrict__ Ah,
              __half* __restrict__ H0, __half* __restrict__ H1, __half* __restrict__ H2,
              float* __restrict__ Cf)
{
    extern __shared__ __half smh[];
    const uint32_t smb = smem_u32(smh);

    const int z = blockIdx.z;
    const float* Af = (z == 0) ? Af0 : (z == 1) ? Af1 : Af2;
    const float* Wf = (z == 0) ? Wf0 : (z == 1) ? Wf1 : Wf2;

    const int tid  = threadIdx.x;
    const int wid  = tid >> 5;
    const int lane = tid & 31;
    const int g    = lane >> 2;
    const int tig  = lane & 3;
    const int wm   = wid & 3;
    const int wn   = wid >> 2;
    const int m0 = blockIdx.y * 128;
    const int n0 = blockIdx.x * 128;

    // staging mapping: 4 threads/row, 16 cols each
    const int lr = tid >> 2;
    const int cq = (tid & 3) * 16;
    const float*  AsrcF = Af + (size_t)(m0 + lr) * DMODEL + cq;
    const __half* AsrcH = Ah + (size_t)(m0 + lr) * DMODEL + cq;   // MODE 1
    const float*  WsrcF = Wf + (size_t)(n0 + lr) * DMODEL + cq;
    __half* const stDstA = smh + lr * GSTR + cq;                  // + buf*2*GBUFH
    __half* const stDstW = stDstA + GBUFH;

    // ldmatrix lane offsets (bytes, within a buffer)
    const uint32_t laneA_off = (uint32_t)(wm*32 + (lane & 15)) * (GSTR*2)
                             + (uint32_t)(lane >> 4) * 16;
    const uint32_t laneB_off = (uint32_t)(wn*32 + (lane & 7) + ((lane >> 4) & 1) * 8) * (GSTR*2)
                             + (uint32_t)((lane >> 3) & 1) * 16;

    float acc[2][4][4];
#pragma unroll
    for (int i = 0; i < 2; i++)
#pragma unroll
        for (int j = 0; j < 4; j++)
#pragma unroll
            for (int q = 0; q < 4; q++) acc[i][j][q] = 0.f;

    // ---- staging helper (convert fp32 -> fp16, or copy fp16) ----
    auto stage = [&](int c, int buf) {
        __half* dA = stDstA + buf * (2*GBUFH);
        __half* dW = stDstW + buf * (2*GBUFH);
        if (MODE == 0) {
            const float4* p = (const float4*)(AsrcF + c*64);
            float4 x0 = p[0], x1 = p[1], x2 = p[2], x3 = p[3];
            ((uint4*)dA)[0] = make_uint4(pack2(x0.x,x0.y), pack2(x0.z,x0.w),
                                         pack2(x1.x,x1.y), pack2(x1.z,x1.w));
            ((uint4*)dA)[1] = make_uint4(pack2(x2.x,x2.y), pack2(x2.z,x2.w),
                                         pack2(x3.x,x3.y), pack2(x3.z,x3.w));
        } else {
            const uint4* p = (const uint4*)(AsrcH + c*64);
            ((uint4*)dA)[0] = p[0];
            ((uint4*)dA)[1] = p[1];
        }
        const float4* pw = (const float4*)(WsrcF + c*64);
        float4 w0 = pw[0], w1 = pw[1], w2 = pw[2], w3 = pw[3];
        ((uint4*)dW)[0] = make_uint4(pack2(w0.x,w0.y), pack2(w0.z,w0.w),
                                     pack2(w1.x,w1.y), pack2(w1.z,w1.w));
        ((uint4*)dW)[1] = make_uint4(pack2(w2.x,w2.y), pack2(w2.z,w2.w),
                                     pack2(w3.x,w3.y), pack2(w3.z,w3.w));
    };

    // prologue: chunks 0,1 -> buffers 0,1
    stage(0, 0);
    stage(1, 1);
    __syncthreads();

    int st = 0;
    for (int c = 0; c < 16; c++) {
        // ---- compute chunk c from buffer st ----
        const uint32_t aBase = smb + st * GSTG + laneA_off;
        const uint32_t bBase = smb + st * GSTG + GBUFH*2 + laneB_off;
#pragma unroll
        for (int kg = 0; kg < 4; kg++) {
            uint32_t a[2][4];
#pragma unroll
            for (int mt = 0; mt < 2; mt++)
                ldsm_x4(a[mt][0], a[mt][1], a[mt][2], a[mt][3],
                        aBase + mt * (16*GSTR*2) + kg*32);
#pragma unroll
            for (int ntp = 0; ntp < 2; ntp++) {
                uint32_t b0, b1, b2, b3;
                ldsm_x4(b0, b1, b2, b3, bBase + ntp * (16*GSTR*2) + kg*32);
#pragma unroll
                for (int mt = 0; mt < 2; mt++) {
                    mma_f16(acc[mt][2*ntp  ], a[mt][0], a[mt][1], a[mt][2], a[mt][3], b0, b1);
                    mma_f16(acc[mt][2*ntp+1], a[mt][0], a[mt][1], a[mt][2], a[mt][3], b2, b3);
                }
            }
        }
        // ---- stage chunk c+2 into buffer st+2 (last read in chunk c-1) ----
        if (c + 2 < 16) {
            int st2 = st + 2; if (st2 >= 3) st2 -= 3;
            stage(c + 2, st2);
        }
        __syncthreads();
        st++; if (st == 3) st = 0;
    }

    const float sc = (MODE == 0 && z == 0) ? QSCALE : 1.0f;
    __half* Hm = (z == 0) ? H0 : (z == 1) ? H1 : H2;
#pragma unroll
    for (int mt = 0; mt < 2; mt++) {
#pragma unroll
        for (int nt = 0; nt < 4; nt++) {
            int m = m0 + wm*32 + mt*16 + g;
            int n = n0 + wn*32 + nt*8 + 2*tig;
#pragma unroll
            for (int half_ = 0; half_ < 2; half_++) {
                int mm = m + half_*8;
                float vx = acc[mt][nt][half_*2];
                float vy = acc[mt][nt][half_*2+1];
                if (MODE == 0) {
                    int b = mm >> 11;
                    int l = mm & (SEQ - 1);
                    int h = n >> 6;
                    int d = n & (HDIM - 1);
                    size_t base = ((size_t)((b*NHEAD + h)*SEQ) + l) * HDIM;
                    *(__half2*)&Hm[base + d] = __floats2half2_rn(vx*sc, vy*sc);
                } else {
                    *(float2*)&Cf[(size_t)mm * DMODEL + n] = make_float2(vx, vy);
                }
            }
        }
    }
}

// =================================================================
// Flash attention v11 (unchanged from R16): fp16, log2 softmax
// (f32 ex2), 256 thr = 8 warps x 16 q, 128 q/block, 64-key chunks,
// 3-stage cp.async K/V pipeline, ldmatrix fragments.
// =================================================================
#define FQS 72
#define FA_Q (128*FQS)                 // 9216 halves
#define FA_K (64*FQS)                  // 4608
#define FA_V (64*FQS)                  // 4608
#define FA_SMEM_BYTES ((FA_Q + 3*FA_K + 3*FA_V)*2)   // 73728 B

__global__ __launch_bounds__(256, 2)
void flash_mma(const int* __restrict__ mask,
               const __half* __restrict__ Qg,
               const __half* __restrict__ Kg,
               const __half* __restrict__ Vg,
               __half* __restrict__ Og)
{
    extern __shared__ __half smh[];
    const uint32_t smb = smem_u32(smh);
    __shared__ int msk[64];

    const int tid  = threadIdx.x;
    const int lane = tid & 31;
    const int wid  = tid >> 5;
    const int g    = lane >> 2;
    const int tig  = lane & 3;
    const int qb   = wid * 16;

    const int bh = blockIdx.y;
    const int b  = bh / NHEAD;
    const int h  = bh % NHEAD;
    const int q0 = blockIdx.x * 128;

    const size_t bhBase = (size_t)(b*NHEAD + h) * SEQ * HDIM;

    const int lr2 = tid >> 2;
    const int cb2 = (tid & 3) * 2;
    const __half* Ksrc = Kg + bhBase + (size_t)lr2 * HDIM + cb2 * 8;
    const __half* Vsrc = Vg + bhBase + (size_t)lr2 * HDIM + cb2 * 8;
    const uint32_t kDst0 = smb + FA_Q*2 + lr2 * (FQS*2) + cb2 * 16;
    const uint32_t vDst0 = smb + (FA_Q + 3*FA_K)*2 + lr2 * (FQS*2) + cb2 * 16;

    const uint32_t laneQ_off = (uint32_t)(qb + (lane & 15)) * (FQS*2)
                             + (uint32_t)(lane >> 4) * 16;
    const uint32_t laneK_off = (uint32_t)((lane & 7) + ((lane >> 4) & 1) * 8) * (FQS*2)
                             + (uint32_t)((lane >> 3) & 1) * 16;
    const uint32_t laneV_off = (uint32_t)(lane & 15) * (FQS*2)
                             + (uint32_t)(lane >> 4) * 16;

    // ---- prologue: G0 = Q, G1 = KV0, G2 = KV1 ----
    {
        const int qr = tid >> 1;
        const int qc = (tid & 1) * 4;
        const __half* qsrc = Qg + bhBase + (size_t)(q0 + qr) * HDIM + qc * 8;
        uint32_t qdst = smb + qr * (FQS*2) + qc * 16;
#pragma unroll
        for (int j = 0; j < 4; j++) cp16(qdst + j*16, qsrc + j*8);
        cp_commit();   // G0
#pragma unroll
        for (int j = 0; j < 2; j++) {
            cp16(kDst0 + j*16, Ksrc + j*8);
            cp16(vDst0 + j*16, Vsrc + j*8);
        }
        cp_commit();   // G1
        const __half* ks1 = Ksrc + 64*HDIM;
        const __half* vs1 = Vsrc + 64*HDIM;
#pragma unroll
        for (int j = 0; j < 2; j++) {
            cp16(kDst0 + FA_K*2 + j*16, ks1 + j*8);
            cp16(vDst0 + FA_V*2 + j*16, vs1 + j*8);
        }
        cp_commit();   // G2
    }

    // ---- whole-sequence mask precheck ----
    int sv = 1;
#pragma unroll
    for (int j = 0; j < 8; j++)
        sv &= (mask[b*SEQ + tid + j*256] != 0);
    const int allSeq = __syncthreads_and(sv);
    int mreg = 0;
    if (!allSeq && tid < 64) mreg = mask[b*SEQ + tid];

    // ---- Q fragments to registers (once) ----
    cp_wait2();
    __syncthreads();
    uint32_t qa[4][4];
#pragma unroll
    for (int kg = 0; kg < 4; kg++)
        ldsm_x4(qa[kg][0], qa[kg][1], qa[kg][2], qa[kg][3],
                smb + laneQ_off + kg*32);

    float o[8][4];
#pragma unroll
    for (int nt = 0; nt < 8; nt++)
#pragma unroll
        for (int q = 0; q < 4; q++) o[nt][q] = 0.f;
    float lrow0 = 0.f, lrow1 = 0.f;
    float mrow0 = -1e30f, mrow1 = -1e30f;

    int st = 0;
    for (int c = 0; c < 32; c++) {
        cp_wait1();
        int allv;
        if (!allSeq) {
            if (tid < 64) msk[tid] = mreg;
            int curv = (tid < 64) ? (mreg != 0) : 1;
            if (c + 1 < 32 && tid < 64) mreg = mask[b*SEQ + (c+1)*64 + tid];
            allv = __syncthreads_and(curv);
        } else {
            __syncthreads();
            allv = 1;
        }

        // issue chunk c+2 (always commit to keep wait accounting)
        {
            int st2 = st + 2; if (st2 >= 3) st2 -= 3;
            if (c + 2 < 32) {
                const __half* ks = Ksrc + (size_t)(c+2) * 64 * HDIM;
                const __half* vs = Vsrc + (size_t)(c+2) * 64 * HDIM;
                const uint32_t kd = kDst0 + st2 * (FA_K*2);
                const uint32_t vd = vDst0 + st2 * (FA_V*2);
#pragma unroll
                for (int j = 0; j < 2; j++) {
                    cp16(kd + j*16, ks + j*8);
                    cp16(vd + j*16, vs + j*8);
                }
            }
            cp_commit();
        }

        const uint32_t kBase = smb + FA_Q*2 + st * (FA_K*2) + laneK_off;

        // ---- S = Q K^T ----
        float s[8][4];
#pragma unroll
        for (int nt = 0; nt < 8; nt++)
#pragma unroll
            for (int q = 0; q < 4; q++) s[nt][q] = 0.f;

#pragma unroll
        for (int kg = 0; kg < 4; kg++) {
#pragma unroll
            for (int ntp = 0; ntp < 4; ntp++) {
                uint32_t b0, b1, b2, b3;
                ldsm_x4(b0, b1, b2, b3, kBase + ntp * (16*FQS*2) + kg*32);
                mma_f16(s[2*ntp  ], qa[kg][0], qa[kg][1], qa[kg][2], qa[kg][3], b0, b1);
                mma_f16(s[2*ntp+1], qa[kg][0], qa[kg][1], qa[kg][2], qa[kg][3], b2, b3);
            }
        }

        // ---- mask (skipped when chunk fully valid) ----
        if (!allv) {
#pragma unroll
            for (int nt = 0; nt < 8; nt++) {
                int j0 = nt*8 + 2*tig;
                bool k0 = (msk[j0]   != 0);
                bool k1 = (msk[j0+1] != 0);
                s[nt][0] = k0 ? s[nt][0] : NEG_INF_V;
                s[nt][1] = k1 ? s[nt][1] : NEG_INF_V;
                s[nt][2] = k0 ? s[nt][2] : NEG_INF_V;
                s[nt][3] = k1 ? s[nt][3] : NEG_INF_V;
            }
        }

        // ---- online softmax (log2 domain, f32 ex2) ----
        float rm0 = -1e30f, rm1 = -1e30f;
#pragma unroll
        for (int nt = 0; nt < 8; nt++) {
            rm0 = fmaxf(rm0, fmaxf(s[nt][0], s[nt][1]));
            rm1 = fmaxf(rm1, fmaxf(s[nt][2], s[nt][3]));
        }
        rm0 = fmaxf(rm0, __shfl_xor_sync(0xffffffffu, rm0, 1));
        rm0 = fmaxf(rm0, __shfl_xor_sync(0xffffffffu, rm0, 2));
        rm1 = fmaxf(rm1, __shfl_xor_sync(0xffffffffu, rm1, 1));
        rm1 = fmaxf(rm1, __shfl_xor_sync(0xffffffffu, rm1, 2));

        float mn0 = fmaxf(mrow0, rm0);
        float mn1 = fmaxf(mrow1, rm1);
        bool stable = __all_sync(0xffffffffu, (mn0 == mrow0) && (mn1 == mrow1));
        if (!stable) {
            float fac0 = ex2f(mrow0 - mn0);
            float fac1 = ex2f(mrow1 - mn1);
            lrow0 *= fac0;
            lrow1 *= fac1;
#pragma unroll
            for (int nt = 0; nt < 8; nt++) {
                o[nt][0] *= fac0; o[nt][1] *= fac0;
                o[nt][2] *= fac1; o[nt][3] *= fac1;
            }
            mrow0 = mn0;
            mrow1 = mn1;
        }

        // exp (f32), row-sum on fma pipe
        float rs0 = 0.f, rs1 = 0.f;
#pragma unroll
        for (int nt = 0; nt < 8; nt++) {
            s[nt][0] = ex2f(s[nt][0] - mrow0);
            s[nt][1] = ex2f(s[nt][1] - mrow0);
            s[nt][2] = ex2f(s[nt][2] - mrow1);
            s[nt][3] = ex2f(s[nt][3] - mrow1);
            rs0 += s[nt][0] + s[nt][1];
            rs1 += s[nt][2] + s[nt][3];
        }
        rs0 += __shfl_xor_sync(0xffffffffu, rs0, 1);
        rs0 += __shfl_xor_sync(0xffffffffu, rs0, 2);
        rs1 += __shfl_xor_sync(0xffffffffu, rs1, 1);
        rs1 += __shfl_xor_sync(0xffffffffu, rs1, 2);
        lrow0 += rs0;
        lrow1 += rs1;

        // ---- O += P V (pack P to fp16; ldmatrix.trans B) ----
        const uint32_t vBase = smb + (FA_Q + 3*FA_K)*2 + st * (FA_V*2) + laneV_off;
#pragma unroll
        for (int kg = 0; kg < 4; kg++) {
            uint32_t a0 = pack2(s[2*kg  ][0], s[2*kg  ][1]);
            uint32_t a1 = pack2(s[2*kg  ][2], s[2*kg  ][3]);
            uint32_t a2 = pack2(s[2*kg+1][0], s[2*kg+1][1]);
            uint32_t a3 = pack2(s[2*kg+1][2], s[2*kg+1][3]);
            const uint32_t rowa = vBase + kg * (16*FQS*2);
#pragma unroll
            for (int ntp = 0; ntp < 4; ntp++) {
                uint32_t r0, r1, r2, r3;
                ldsm_x4_t(r0, r1, r2, r3, rowa + ntp*32);
                mma_f16(o[2*ntp  ], a0, a1, a2, a3, r0, r1);
                mma_f16(o[2*ntp+1], a0, a1, a2, a3, r2, r3);
            }
        }

        st++; if (st == 3) st = 0;
    }

    // ---- epilogue: normalize, fp16 -> g_O [B,L,D] (natural) ----
    float inv0 = 1.f / lrow0;
    float inv1 = 1.f / lrow1;
    int qg0 = q0 + qb + g;
    int qg1 = qg0 + 8;
#pragma unroll
    for (int nt = 0; nt < 8; nt++) {
        int pos = h*HDIM + nt*8 + 2*tig;
        *(__half2*)&Og[(size_t)(b*SEQ + qg0)*DMODEL + pos] =
            __floats2half2_rn(o[nt][0]*inv0, o[nt][1]*inv0);
        *(__half2*)&Og[(size_t)(b*SEQ + qg1)*DMODEL + pos] =
            __floats2half2_rn(o[nt][2]*inv1, o[nt][3]*inv1);
    }
}

// =================================================================
// Host launcher
// =================================================================
extern "C" void kernel_launch(void* const* d_in, const int* in_sizes, int n_in,
                              void* d_out, int out_size)
{
    const float* q    = (const float*)d_in[0];
    const float* k    = (const float*)d_in[1];
    const float* v    = (const float*)d_in[2];
    const int*   am   = (const int*)  d_in[3];
    const float* Wq   = (const float*)d_in[4];
    const float* Wk   = (const float*)d_in[5];
    const float* Wv   = (const float*)d_in[6];
    const float* Wo   = (const float*)d_in[7];
    float* out = (float*)d_out;

    __half *gQ, *gK, *gV, *gO;
    cudaGetSymbolAddress((void**)&gQ, g_Q);
    cudaGetSymbolAddress((void**)&gK, g_K);
    cudaGetSymbolAddress((void**)&gV, g_V);
    cudaGetSymbolAddress((void**)&gO, g_O);

    cudaFuncSetAttribute(gemm_mma<0>, cudaFuncAttributeMaxDynamicSharedMemorySize, GT_SMEM_BYTES);
    cudaFuncSetAttribute(gemm_mma<1>, cudaFuncAttributeMaxDynamicSharedMemorySize, GT_SMEM_BYTES);
    cudaFuncSetAttribute(flash_mma,   cudaFuncAttributeMaxDynamicSharedMemorySize, FA_SMEM_BYTES);

    // fused QKV projections with inline fp32->fp16 conversion (no prep)
    dim3 gGrid(DMODEL/128, MROWS/128, 3);  // (8, 32, 3)
    gemm_mma<0><<<gGrid, 512, GT_SMEM_BYTES>>>(q, k, v, Wq, Wk, Wv,
                                               gO /*unused*/, gQ, gK, gV, out);

    dim3 aGrid(SEQ/128, BATCH*NHEAD);      // (16, 32)
    flash_mma<<<aGrid, 256, FA_SMEM_BYTES>>>(am, gQ, gK, gV, gO);

    dim3 oGrid(DMODEL/128, MROWS/128, 1);  // (8, 32)
    gemm_mma<1><<<oGrid, 512, GT_SMEM_BYTES>>>(q, q, q, Wo, Wo, Wo,
                                               gO, gQ, gK, gV, out);
}